// round 7
// baseline (speedup 1.0000x reference)
#include <cuda_runtime.h>
#include <cuda_bf16.h>
#include <cuda_pipeline_primitives.h>
#include <math_constants.h>

// Problem: cummax along axis=2 of x[B=8, Tt=128, Ts=128, C=512] fp32.
// out[b,t,j,c] = max_{j'<=j} x[b,t,j',c]
//
// R6: cp.async (LDGSTS) staged pipeline. ptxas refuses to allocate regs for
// batched LDG (R4/R5 both compiled to regs=32, MLP_eff~4). LDGSTS has no
// destination register, so pipeline depth is structural: STAGES*JB = 12
// outstanding 16B loads per thread, independent of reg allocation.
// Smem slots are per-thread-private -> no __syncthreads, no bank conflicts.

static __device__ __forceinline__ float4 f4max(float4 a, float4 b) {
    float4 r;
    r.x = fmaxf(a.x, b.x);
    r.y = fmaxf(a.y, b.y);
    r.z = fmaxf(a.z, b.z);
    r.w = fmaxf(a.w, b.w);
    return r;
}

constexpr int THREADS = 256;
constexpr int TS      = 128;
constexpr int C4      = 128;   // 512 channels / 4 floats
constexpr int JB      = 4;     // j-steps per stage
constexpr int STAGES  = 3;     // pipeline depth
constexpr int NSTAGE  = TS / JB;  // 32

__global__ void __launch_bounds__(THREADS) cummax_kernel(
    const float4* __restrict__ in, float4* __restrict__ out)
{
    // 3 * 4 * 256 * 16B = 48 KB (static smem limit)
    __shared__ float4 buf[STAGES][JB][THREADS];

    const int tid = threadIdx.x;
    const int col = blockIdx.x * THREADS + tid;   // 0..131071
    const int bt  = col >> 7;                     // (b,t) row
    const int c4  = col & 127;                    // float4 within C

    const float4* __restrict__ p = in  + (size_t)bt * TS * C4 + c4;
    float4* __restrict__       q = out + (size_t)bt * TS * C4 + c4;

    // Prime the pipeline: STAGES commit-groups, JB cp.asyncs each.
    #pragma unroll
    for (int s = 0; s < STAGES; ++s) {
        #pragma unroll
        for (int u = 0; u < JB; ++u) {
            __pipeline_memcpy_async(&buf[s][u][tid],
                                    p + (size_t)(s * JB + u) * C4,
                                    sizeof(float4));
        }
        __pipeline_commit();
    }

    float4 m = make_float4(-CUDART_INF_F, -CUDART_INF_F,
                           -CUDART_INF_F, -CUDART_INF_F);

    #pragma unroll 1
    for (int s = 0; s < NSTAGE; ++s) {
        // Wait until only STAGES-1 groups are still in flight -> stage s done.
        __pipeline_wait_prior(STAGES - 1);

        const int sb = s % STAGES;
        const size_t jbase = (size_t)(s * JB) * C4;

        // Consume stage s from smem: LDS.128, running max, STG.128 burst.
        #pragma unroll
        for (int u = 0; u < JB; ++u) {
            float4 v = buf[sb][u][tid];
            m = f4max(m, v);
            q[jbase + (size_t)u * C4] = m;
        }

        // Refill this buffer with stage s+STAGES (program order guarantees
        // the LDS reads above are ordered before these same-address writes).
        const int sn = s + STAGES;
        if (sn < NSTAGE) {
            #pragma unroll
            for (int u = 0; u < JB; ++u) {
                __pipeline_memcpy_async(&buf[sb][u][tid],
                                        p + (size_t)(sn * JB + u) * C4,
                                        sizeof(float4));
            }
        }
        // Commit even when empty to keep the group count in lockstep.
        __pipeline_commit();
    }
}

extern "C" void kernel_launch(void* const* d_in, const int* in_sizes, int n_in,
                              void* d_out, int out_size)
{
    const float4* x = (const float4*)d_in[0];
    float4* y = (float4*)d_out;

    const int total_cols = 8 * 128 * (512 / 4);   // 131072
    const int blocks = total_cols / THREADS;      // 512
    cummax_kernel<<<blocks, THREADS>>>(x, y);
}

// round 8
// speedup vs baseline: 1.0495x; 1.0495x over previous
#include <cuda_runtime.h>
#include <cuda_bf16.h>

// Problem: cummax along axis=2 of x[B=8, Tt=128, Ts=128, C=512] fp32.
// out[b,t,j,c] = max_{j'<=j} x[b,t,j',c]
//
// R7: CTA->SM load balance fix. Previous grids (512 CTAs, all resident in
// wave 1) froze a 4-vs-3 CTA split across SMs (max/avg = 1.156 -> ~15%
// structural slack, matching the stubborn ~75% DRAM plateau).
// Now: 1024 CTAs x 128 threads, one CTA per (b,t) row. 1024/148 = 6.92,
// per-SM split 7-vs-6 -> 1.2% slack. Kernel body identical to the proven
// R1 form (float4, unroll 8, no cache hints, no smem).

static __device__ __forceinline__ float4 f4max(float4 a, float4 b) {
    float4 r;
    r.x = fmaxf(a.x, b.x);
    r.y = fmaxf(a.y, b.y);
    r.z = fmaxf(a.z, b.z);
    r.w = fmaxf(a.w, b.w);
    return r;
}

// One CTA per (b,t) row: 128 threads cover the 128 float4 channel groups.
// Each thread walks j = 0..127 (stride 2KB) with a register running max.
__global__ void __launch_bounds__(128) cummax_kernel(
    const float4* __restrict__ in, float4* __restrict__ out)
{
    constexpr int TS = 128;
    constexpr int C4 = 128;               // 512 channels / 4
    const int bt = blockIdx.x;            // (b,t) row, 0..1023
    const int c4 = threadIdx.x;           // float4 within C, 0..127

    const float4* __restrict__ p = in  + (size_t)bt * TS * C4 + c4;
    float4* __restrict__       q = out + (size_t)bt * TS * C4 + c4;

    float4 m = p[0];
    q[0] = m;

    #pragma unroll 8
    for (int j = 1; j < TS; ++j) {
        float4 v = p[(size_t)j * C4];
        m = f4max(m, v);
        q[(size_t)j * C4] = m;
    }
}

extern "C" void kernel_launch(void* const* d_in, const int* in_sizes, int n_in,
                              void* d_out, int out_size)
{
    const float4* x = (const float4*)d_in[0];
    float4* y = (float4*)d_out;

    // 1024 CTAs = B*Tt rows; 128 threads = C/4 float4 columns per row.
    cummax_kernel<<<1024, 128>>>(x, y);
}